// round 7
// baseline (speedup 1.0000x reference)
#include <cuda_runtime.h>
#include <cuda_bf16.h>
#include <math.h>
#include <stdint.h>

#define Bb    512
#define Tt    32
#define DEPTH 512
#define RNN   512
#define NCC   128
#define G4    2048
#define BT    16384
#define BRNN  (Bb*RNN)
#define SMEM_Z    197632   // mode0: 2 x 96KB + align
#define SMEM_STEP 148480   // step : 2 x 72KB + align

// ---------------- device scratch -------------------------------------------
__device__ float g_Z[BT * G4];                 // gates from X@W+bias, cols n'=r*4+g
__device__ float g_hall[(Tt + 1) * BRNN];      // h per step (slots 1..32 used)
__device__ float g_c0[BRNN];
__device__ float g_c1[BRNN];
// bf16 3-way splits as pre-swizzled SW128 tile images
__device__ __align__(16) unsigned short g_Xs[3 * 128 * 10 * 8192]; // [3][128 mt(128r)][10 ch] 16KB
__device__ __align__(16) unsigned short g_Ws[3 * 16 * 10 * 8192];  // [3][16 nt][10 ch] 16KB (n' cols)
__device__ __align__(16) unsigned short g_Rs[3 * 16 * 8 * 8192];   // [3][16 nt][8 ch] 16KB (n' cols)
__device__ __align__(16) unsigned short g_hs[3 * 8 * 8 * 4096];    // [3][8 mt(64 b)][8 ch] 8KB

// ---------------- PTX helpers ----------------------------------------------
static __device__ __forceinline__ uint32_t s2u(const void* p) {
    uint32_t a;
    asm("{ .reg .u64 t; cvta.to.shared.u64 t, %1; cvt.u32.u64 %0, t; }" : "=r"(a) : "l"(p));
    return a;
}
static __device__ __forceinline__ void cp16(uint32_t d, const void* s) {
    asm volatile("cp.async.cg.shared.global [%0], [%1], 16;" :: "r"(d), "l"(s));
}
#define CP_COMMIT() asm volatile("cp.async.commit_group;" ::: "memory")
#define CP_WAIT(n)  asm volatile("cp.async.wait_group %0;" :: "n"(n) : "memory")

static __device__ __forceinline__ void ldsm4(uint32_t* r, uint32_t a) {
    asm volatile("ldmatrix.sync.aligned.m8n8.x4.shared.b16 {%0,%1,%2,%3}, [%4];"
        : "=r"(r[0]), "=r"(r[1]), "=r"(r[2]), "=r"(r[3]) : "r"(a));
}
static __device__ __forceinline__ void ldsm2(uint32_t* r, uint32_t a) {
    asm volatile("ldmatrix.sync.aligned.m8n8.x2.shared.b16 {%0,%1}, [%2];"
        : "=r"(r[0]), "=r"(r[1]) : "r"(a));
}
static __device__ __forceinline__ void mma16816(float* d, const uint32_t* a, const uint32_t* b) {
    asm volatile("mma.sync.aligned.m16n8k16.row.col.f32.bf16.bf16.f32 "
        "{%0,%1,%2,%3}, {%4,%5,%6,%7}, {%8,%9}, {%0,%1,%2,%3};"
        : "+f"(d[0]), "+f"(d[1]), "+f"(d[2]), "+f"(d[3])
        : "r"(a[0]), "r"(a[1]), "r"(a[2]), "r"(a[3]), "r"(b[0]), "r"(b[1]));
}

// ---------------- split helpers --------------------------------------------
static __device__ __forceinline__ void split3(float x, unsigned short& s1,
                                              unsigned short& s2, unsigned short& s3) {
    __nv_bfloat16 b1 = __float2bfloat16_rn(x);
    float r1 = x - __bfloat162float(b1);
    __nv_bfloat16 b2 = __float2bfloat16_rn(r1);
    float r2 = r1 - __bfloat162float(b2);
    __nv_bfloat16 b3 = __float2bfloat16_rn(r2);
    s1 = __bfloat16_as_ushort(b1); s2 = __bfloat16_as_ushort(b2); s3 = __bfloat16_as_ushort(b3);
}
static __device__ __forceinline__ uint32_t swz(uint32_t o) { return o ^ ((o >> 3) & 0x70); }
// write one float4's 3 splits into [128 x 64bf16] SW128 tile images (16KB each)
static __device__ __forceinline__ void put_split4(char* base, int s_mul, int mt, int nch,
                                                  int c, int rb, int kk, float4 v) {
    uint32_t sw = swz(((uint32_t)(rb >> 3) << 10) + ((uint32_t)(rb & 7) << 7) + ((uint32_t)kk << 1));
    float xs[4] = {v.x, v.y, v.z, v.w};
    unsigned short a[3][4];
    #pragma unroll
    for (int i = 0; i < 4; i++) split3(xs[i], a[0][i], a[1][i], a[2][i]);
    #pragma unroll
    for (int s = 0; s < 3; s++) {
        ushort4 o = make_ushort4(a[s][0], a[s][1], a[s][2], a[s][3]);
        *(ushort4*)(base + ((size_t)(s * s_mul + mt) * nch + c) * 16384 + sw) = o;
    }
}
__device__ __forceinline__ float sigm(float x) { return 1.f / (1.f + expf(-x)); }

// ---------------- prep kernels ----------------------------------------------
__global__ void assemble_splitX_kernel(const float* __restrict__ f_pool,
                                       const float* __restrict__ gt) {
    int idx = blockIdx.x * blockDim.x + threadIdx.x;
    if (idx >= BT * 160) return;
    int r = idx / 160, k0 = (idx - r * 160) * 4;
    float4 v;
    if (k0 < DEPTH) v = *(const float4*)(f_pool + (size_t)r * DEPTH + k0);
    else {
        int t = r & 31;
        v = (t == 0) ? make_float4(0.f, 0.f, 0.f, 0.f)
                     : *(const float4*)(gt + (size_t)(r - 1) * NCC + (k0 - DEPTH));
    }
    put_split4((char*)g_Xs, 128, r >> 7, 10, k0 >> 6, r & 127, k0 & 63, v);
}

// W, rec: columns permuted n -> n' = r*4+g (n = g*512 + r)
__global__ void split_W_kernel(const float* __restrict__ W) {
    int idx = blockIdx.x * blockDim.x + threadIdx.x;
    if (idx >= 160 * 2048) return;
    int kc = idx >> 11, n = idx & 2047, k0 = kc * 4;
    int g = n >> 9, r = n & 511, np = r * 4 + g;
    float4 v;
    v.x = W[(size_t)(k0 + 0) * G4 + n]; v.y = W[(size_t)(k0 + 1) * G4 + n];
    v.z = W[(size_t)(k0 + 2) * G4 + n]; v.w = W[(size_t)(k0 + 3) * G4 + n];
    put_split4((char*)g_Ws, 16, np >> 7, 10, k0 >> 6, np & 127, k0 & 63, v);
}

__global__ void split_rec_kernel(const float* __restrict__ rec) {
    int idx = blockIdx.x * blockDim.x + threadIdx.x;
    if (idx >= 128 * 2048) return;
    int kc = idx >> 11, n = idx & 2047, k0 = kc * 4;
    int g = n >> 9, r = n & 511, np = r * 4 + g;
    float4 v;
    v.x = rec[(size_t)(k0 + 0) * G4 + n]; v.y = rec[(size_t)(k0 + 1) * G4 + n];
    v.z = rec[(size_t)(k0 + 2) * G4 + n]; v.w = rec[(size_t)(k0 + 3) * G4 + n];
    put_split4((char*)g_Rs, 16, np >> 7, 8, k0 >> 6, np & 127, k0 & 63, v);
}

// ============ mode0: g_Z = X@W + bias (128x128 tiles, 6-product bf16) =======
__global__ __launch_bounds__(256) void hmma_Z_kernel(const float* __restrict__ bias) {
    extern __shared__ char dsm[];
    const char* A8 = (const char*)g_Xs;
    const char* B8 = (const char*)g_Ws;
    const int tid = threadIdx.x, lane = tid & 31, wid = tid >> 5;
    const int mt = blockIdx.y, nt = blockIdx.x;
    const int wm = wid & 1, wn = wid >> 1;
    uint32_t buf0 = (s2u(dsm) + 1023u) & ~1023u;

    const int l7 = lane & 7;
    const uint32_t xm = (uint32_t)l7 << 4;
    const int asub = lane >> 3;
    const uint32_t akoff = (uint32_t)(asub >> 1) * 16;
    const uint32_t bkoff = (uint32_t)((lane >> 3) & 1) * 16;
    uint32_t arb[4], brb[4];
    #pragma unroll
    for (int m4 = 0; m4 < 4; m4++) {
        int row = wm * 64 + m4 * 16 + (asub & 1) * 8 + l7;
        arb[m4] = (uint32_t)(row >> 3) * 1024u + (uint32_t)l7 * 128u;
    }
    #pragma unroll
    for (int n4 = 0; n4 < 4; n4++) {
        int row = wn * 32 + n4 * 8 + l7;
        brb[n4] = (uint32_t)(row >> 3) * 1024u + (uint32_t)l7 * 128u + 49152u;
    }

    float acc[4][4][4];
    #pragma unroll
    for (int m4 = 0; m4 < 4; m4++)
        #pragma unroll
        for (int n4 = 0; n4 < 4; n4++)
            #pragma unroll
            for (int e = 0; e < 4; e++) acc[m4][n4][e] = 0.f;

    auto load_chunk = [&](int c, int bb) {
        uint32_t sb = buf0 + (uint32_t)bb * 98304u;
        #pragma unroll
        for (int tau = 0; tau < 6; tau++) {
            const char* g = (tau < 3)
                ? A8 + ((size_t)(tau * 128 + mt) * 10 + c) * 16384
                : B8 + ((size_t)((tau - 3) * 16 + nt) * 10 + c) * 16384;
            uint32_t sdst = sb + (uint32_t)tau * 16384u + (uint32_t)tid * 16u;
            const char* gs = g + tid * 16;
            #pragma unroll
            for (int u = 0; u < 4; u++) cp16(sdst + u * 4096u, gs + u * 4096);
        }
    };

    load_chunk(0, 0);
    CP_COMMIT();
    for (int c = 0; c < 10; c++) {
        int cur = c & 1;
        if (c + 1 < 10) { load_chunk(c + 1, cur ^ 1); CP_COMMIT(); CP_WAIT(1); }
        else CP_WAIT(0);
        __syncthreads();
        uint32_t sb = buf0 + (uint32_t)cur * 98304u;
        #pragma unroll
        for (int ks = 0; ks < 4; ks++) {
            uint32_t kb = (uint32_t)ks * 32;
            uint32_t a[3][4][4];
            #pragma unroll
            for (int s = 0; s < 3; s++) {
                uint32_t ab = sb + (uint32_t)s * 16384u + ((kb + akoff) ^ xm);
                #pragma unroll
                for (int m4 = 0; m4 < 4; m4++) ldsm4(a[s][m4], ab + arb[m4]);
            }
            #pragma unroll
            for (int j = 0; j < 3; j++) {
                uint32_t b[4][2];
                uint32_t bbq = sb + (uint32_t)j * 16384u + ((kb + bkoff) ^ xm);
                #pragma unroll
                for (int n4 = 0; n4 < 4; n4++) ldsm2(b[n4], bbq + brb[n4]);
                #pragma unroll
                for (int i = 0; i + j < 3; i++)
                    #pragma unroll
                    for (int m4 = 0; m4 < 4; m4++)
                        #pragma unroll
                        for (int n4 = 0; n4 < 4; n4++)
                            mma16816(acc[m4][n4], a[i][m4], b[n4]);
            }
        }
        __syncthreads();
    }

    #pragma unroll
    for (int m4 = 0; m4 < 4; m4++) {
        int grow = mt * 128 + wm * 64 + m4 * 16 + (lane >> 2);
        #pragma unroll
        for (int n4 = 0; n4 < 4; n4++) {
            int gcol = nt * 128 + wn * 32 + n4 * 8 + (lane & 3) * 2;
            // bias permute: n' -> n = (n'&3)*512 + (n'>>2)
            float b0 = bias[(gcol & 3) * 512 + (gcol >> 2)];
            float b1 = bias[((gcol + 1) & 3) * 512 + ((gcol + 1) >> 2)];
            float2 v;
            v.x = acc[m4][n4][0] + b0; v.y = acc[m4][n4][1] + b1;
            *(float2*)(g_Z + (size_t)grow * G4 + gcol) = v;
            v.x = acc[m4][n4][2] + b0; v.y = acc[m4][n4][3] + b1;
            *(float2*)(g_Z + (size_t)(grow + 8) * G4 + gcol) = v;
        }
    }
}

// ============ fused LSTM step: h@rec + Z + gating + h-splits ================
// 64x128 tile, grid(16 nt, 8 mt), K=512 (8 chunks), cols n'=r*4+g.
__global__ __launch_bounds__(256) void hmma_step_kernel(int t) {
    extern __shared__ char dsm[];
    const char* A8 = (const char*)g_hs;
    const char* B8 = (const char*)g_Rs;
    const int tid = threadIdx.x, lane = tid & 31, wid = tid >> 5;
    const int mt = blockIdx.y, nt = blockIdx.x;
    const int wm = wid & 1, wn = wid >> 1;    // warp tile 32x32
    uint32_t buf0 = (s2u(dsm) + 1023u) & ~1023u;

    const int l7 = lane & 7;
    const uint32_t xm = (uint32_t)l7 << 4;
    const int asub = lane >> 3;
    const uint32_t akoff = (uint32_t)(asub >> 1) * 16;
    const uint32_t bkoff = (uint32_t)((lane >> 3) & 1) * 16;
    uint32_t arb[2], brb[4];
    #pragma unroll
    for (int m4 = 0; m4 < 2; m4++) {
        int row = wm * 32 + m4 * 16 + (asub & 1) * 8 + l7;   // < 64
        arb[m4] = (uint32_t)(row >> 3) * 1024u + (uint32_t)l7 * 128u;
    }
    #pragma unroll
    for (int n4 = 0; n4 < 4; n4++) {
        int row = wn * 32 + n4 * 8 + l7;                     // < 128
        brb[n4] = (uint32_t)(row >> 3) * 1024u + (uint32_t)l7 * 128u + 24576u;
    }

    float acc[2][4][4];
    #pragma unroll
    for (int m4 = 0; m4 < 2; m4++)
        #pragma unroll
        for (int n4 = 0; n4 < 4; n4++)
            #pragma unroll
            for (int e = 0; e < 4; e++) acc[m4][n4][e] = 0.f;

    auto load_chunk = [&](int c, int bb) {
        uint32_t sb = buf0 + (uint32_t)bb * 73728u;
        #pragma unroll
        for (int s = 0; s < 3; s++) {  // A: 8KB images
            const char* g = A8 + ((size_t)(s * 8 + mt) * 8 + c) * 8192;
            uint32_t sdst = sb + (uint32_t)s * 8192u + (uint32_t)tid * 16u;
            const char* gs = g + tid * 16;
            #pragma unroll
            for (int u = 0; u < 2; u++) cp16(sdst + u * 4096u, gs + u * 4096);
        }
        #pragma unroll
        for (int s = 0; s < 3; s++) {  // B: 16KB images
            const char* g = B8 + ((size_t)(s * 16 + nt) * 8 + c) * 16384;
            uint32_t sdst = sb + 24576u + (uint32_t)s * 16384u + (uint32_t)tid * 16u;
            const char* gs = g + tid * 16;
            #pragma unroll
            for (int u = 0; u < 4; u++) cp16(sdst + u * 4096u, gs + u * 4096);
        }
    };

    load_chunk(0, 0);
    CP_COMMIT();
    for (int c = 0; c < 8; c++) {
        int cur = c & 1;
        if (c + 1 < 8) { load_chunk(c + 1, cur ^ 1); CP_COMMIT(); CP_WAIT(1); }
        else CP_WAIT(0);
        __syncthreads();
        uint32_t sb = buf0 + (uint32_t)cur * 73728u;
        #pragma unroll
        for (int ks = 0; ks < 4; ks++) {
            uint32_t kb = (uint32_t)ks * 32;
            uint32_t a[3][2][4];
            #pragma unroll
            for (int s = 0; s < 3; s++) {
                uint32_t ab = sb + (uint32_t)s * 8192u + ((kb + akoff) ^ xm);
                #pragma unroll
                for (int m4 = 0; m4 < 2; m4++) ldsm4(a[s][m4], ab + arb[m4]);
            }
            #pragma unroll
            for (int j = 0; j < 3; j++) {
                uint32_t b[4][2];
                uint32_t bbq = sb + (uint32_t)j * 16384u + ((kb + bkoff) ^ xm);
                #pragma unroll
                for (int n4 = 0; n4 < 4; n4++) ldsm2(b[n4], bbq + brb[n4]);
                #pragma unroll
                for (int i = 0; i + j < 3; i++)
                    #pragma unroll
                    for (int m4 = 0; m4 < 2; m4++)
                        #pragma unroll
                        for (int n4 = 0; n4 < 4; n4++)
                            mma16816(acc[m4][n4], a[i][m4], b[n4]);
            }
        }
        __syncthreads();
    }

    // fused gating epilogue
    const float* __restrict__ c_prev = (t & 1) ? g_c1 : g_c0;
    float* __restrict__ c_out = (t & 1) ? g_c0 : g_c1;
    float* __restrict__ h_out = g_hall + (size_t)(t + 1) * BRNN;
    const int x = lane & 3;
    const bool evn = (lane & 1) == 0;
    char* hb = (char*)g_hs;

    #pragma unroll
    for (int m4 = 0; m4 < 2; m4++) {
        int rowA = mt * 64 + wm * 32 + m4 * 16 + (lane >> 2);
        #pragma unroll
        for (int n4 = 0; n4 < 4; n4++) {
            float v0 = acc[m4][n4][0], v1 = acc[m4][n4][1];
            float v2 = acc[m4][n4][2], v3 = acc[m4][n4][3];
            float r0 = __shfl_xor_sync(0xffffffffu, v0, 1);
            float r1 = __shfl_xor_sync(0xffffffffu, v1, 1);
            float r2 = __shfl_xor_sync(0xffffffffu, v2, 1);
            float r3 = __shfl_xor_sync(0xffffffffu, v3, 1);
            int b = evn ? rowA : rowA + 8;
            float gi, gf, gg, go;
            if (evn) { gi = v0; gf = v1; gg = r0; go = r1; }
            else     { gi = r2; gf = r3; gg = v2; go = v3; }
            int rloc = wn * 32 + n4 * 8 + (x >> 1) * 4;   // gate-group base col
            int rg = nt * 32 + (rloc >> 2);
            float4 z = *(const float4*)(g_Z + ((size_t)b * Tt + t) * G4 + nt * 128 + rloc);
            gi += z.x; gf += z.y; gg += z.z; go += z.w;
            float c2 = sigm(gf) * c_prev[b * RNN + rg] + sigm(gi) * tanhf(gg);
            float h2 = sigm(go) * tanhf(c2);
            c_out[b * RNN + rg] = c2;
            h_out[(size_t)b * RNN + rg] = h2;
            unsigned short s1, s2, s3;
            split3(h2, s1, s2, s3);
            uint32_t sw = swz(((uint32_t)((b & 63) >> 3) << 10) + ((uint32_t)(b & 7) << 7)
                              + ((uint32_t)(rg & 63) << 1));
            *(unsigned short*)(hb + ((size_t)(0 * 8 + (b >> 6)) * 8 + (rg >> 6)) * 8192 + sw) = s1;
            *(unsigned short*)(hb + ((size_t)(1 * 8 + (b >> 6)) * 8 + (rg >> 6)) * 8192 + sw) = s2;
            *(unsigned short*)(hb + ((size_t)(2 * 8 + (b >> 6)) * 8 + (rg >> 6)) * 8192 + sw) = s3;
        }
    }
}

// ---------------- t=0 gate (h0=c0=0): Z only -> h, c, h-splits --------------
__global__ __launch_bounds__(256) void gate0_kernel() {
    int idx = blockIdx.x * blockDim.x + threadIdx.x;
    if (idx >= Bb * (RNN / 4)) return;
    int r4 = (idx & 127) * 4, b = idx >> 7;
    float* __restrict__ c_out = g_c1;                 // t=0 even -> writes c1
    float* __restrict__ h_out = g_hall + BRNN;        // slot 1
    const float* zb = g_Z + ((size_t)b * Tt) * G4 + r4 * 4;
    float hv[4];
    #pragma unroll
    for (int u = 0; u < 4; u++) {
        float4 z = *(const float4*)(zb + u * 4);      // (i,f,g,o) contiguous
        float c2 = sigm(z.x) * tanhf(z.z);            // c_prev = 0
        float h2 = sigm(z.w) * tanhf(c2);
        c_out[b * RNN + r4 + u] = c2;
        h_out[(size_t)b * RNN + r4 + u] = h2;
        hv[u] = h2;
    }
    // h splits (ushort4 across 4 consecutive r)
    unsigned short a[3][4];
    #pragma unroll
    for (int u = 0; u < 4; u++) split3(hv[u], a[0][u], a[1][u], a[2][u]);
    uint32_t sw = swz(((uint32_t)((b & 63) >> 3) << 10) + ((uint32_t)(b & 7) << 7)
                      + ((uint32_t)(r4 & 63) << 1));
    char* hb = (char*)g_hs;
    #pragma unroll
    for (int s = 0; s < 3; s++) {
        ushort4 o = make_ushort4(a[s][0], a[s][1], a[s][2], a[s][3]);
        *(ushort4*)(hb + ((size_t)(s * 8 + (b >> 6)) * 8 + (r4 >> 6)) * 8192 + sw) = o;
    }
}

// ---------------- logits + argmax (exact fp32, 64-row tiles, 256 CTAs) ------
__global__ __launch_bounds__(256) void logits_argmax_kernel(
    const float* __restrict__ sw_, const float* __restrict__ sb_, float* __restrict__ out) {
    __shared__ float As[2][8][68];
    __shared__ float Bs[2][8][128];
    const int by = blockIdx.x, tid = threadIdx.x;
    const int tx = tid & 15, ty = tid >> 4;
    const int la_r = tid >> 2, la_k = (tid & 3) * 2;
    const int lb_k = tid >> 5, lb_j = (tid & 31) * 4;
    const float* Aptr = g_hall + BRNN + (size_t)(by * 64 + la_r) * RNN + la_k;
    const float* Bptr = sw_ + (size_t)lb_k * NCC + lb_j;

    float acc[4][8];
    #pragma unroll
    for (int i = 0; i < 4; i++)
        #pragma unroll
        for (int j = 0; j < 8; j++) acc[i][j] = 0.f;

    float2 aN = *(const float2*)(Aptr);
    float4 bN = *(const float4*)(Bptr);
    int buf = 0;
    for (int k0 = 0; k0 < RNN; k0 += 8) {
        As[buf][la_k + 0][la_r] = aN.x; As[buf][la_k + 1][la_r] = aN.y;
        *(float4*)&Bs[buf][lb_k][lb_j] = bN;
        if (k0 + 8 < RNN) {
            aN = *(const float2*)(Aptr + k0 + 8);
            bN = *(const float4*)(Bptr + (size_t)(k0 + 8) * NCC);
        }
        __syncthreads();
        #pragma unroll
        for (int kk = 0; kk < 8; kk++) {
            float av[4], bv[8];
            #pragma unroll
            for (int i = 0; i < 4; i++) av[i] = As[buf][kk][ty * 4 + i];
            #pragma unroll
            for (int j = 0; j < 8; j++) bv[j] = Bs[buf][kk][tx * 8 + j];
            #pragma unroll
            for (int i = 0; i < 4; i++)
                #pragma unroll
                for (int j = 0; j < 8; j++) acc[i][j] += av[i] * bv[j];
        }
        buf ^= 1;
    }
    #pragma unroll
    for (int i = 0; i < 4; i++) {
        float best = -1e30f; int bidx = 0;
        #pragma unroll
        for (int j = 0; j < 8; j++) {
            float v = acc[i][j] + sb_[tx * 8 + j];
            if (v > best) { best = v; bidx = tx * 8 + j; }
        }
        #pragma unroll
        for (int off = 8; off >= 1; off >>= 1) {
            float ob = __shfl_xor_sync(0xffffffffu, best, off);
            int oi = __shfl_xor_sync(0xffffffffu, bidx, off);
            if (ob > best || (ob == best && oi < bidx)) { best = ob; bidx = oi; }
        }
        int R = by * 64 + ty * 4 + i;     // R = t*512 + b
        int t = R >> 9, b = R & 511;
        float* orow = out + (size_t)b * (Tt * NCC) + t * NCC;
        #pragma unroll
        for (int j = 0; j < 8; j++) { int col = tx * 8 + j; orow[col] = (col == bidx) ? 1.f : 0.f; }
    }
}

__global__ void copy_final_kernel(float* __restrict__ out) {
    int i = blockIdx.x * blockDim.x + threadIdx.x;
    if (i < BRNN) {
        out[BT * NCC + i] = g_hall[(size_t)Tt * BRNN + i];
        out[BT * NCC + BRNN + i] = g_c0[i];   // t=31 odd -> wrote g_c0
    }
}

// ---------------- launch -----------------------------------------------------
extern "C" void kernel_launch(void* const* d_in, const int* in_sizes, int n_in,
                              void* d_out, int out_size) {
    const float* f_pool = (const float*)d_in[0];
    const float* gt     = (const float*)d_in[1];
    const float* W      = (const float*)d_in[2];
    const float* rec    = (const float*)d_in[3];
    const float* bias   = (const float*)d_in[4];
    const float* sw_    = (const float*)d_in[5];
    const float* sb_    = (const float*)d_in[6];
    float* out = (float*)d_out;

    cudaFuncSetAttribute(hmma_Z_kernel, cudaFuncAttributeMaxDynamicSharedMemorySize, SMEM_Z);
    cudaFuncSetAttribute(hmma_step_kernel, cudaFuncAttributeMaxDynamicSharedMemorySize, SMEM_STEP);

    assemble_splitX_kernel<<<(BT * 160 + 255) / 256, 256>>>(f_pool, gt);
    split_W_kernel<<<(160 * 2048 + 255) / 256, 256>>>(W);
    split_rec_kernel<<<(128 * 2048 + 255) / 256, 256>>>(rec);

    hmma_Z_kernel<<<dim3(16, 128), 256, SMEM_Z>>>(bias);

    gate0_kernel<<<(Bb * (RNN / 4) + 255) / 256, 256>>>();
    for (int t = 1; t < Tt; t++)
        hmma_step_kernel<<<dim3(16, 8), 256, SMEM_STEP>>>(t);

    logits_argmax_kernel<<<256, 256>>>(sw_, sb_, out);
    copy_final_kernel<<<(BRNN + 255) / 256, 256>>>(out);
}

// round 8
// speedup vs baseline: 1.0656x; 1.0656x over previous
#include <cuda_runtime.h>
#include <cuda_bf16.h>
#include <math.h>
#include <stdint.h>

#define Bb    512
#define Tt    32
#define DEPTH 512
#define RNN   512
#define NCC   128
#define G4    2048
#define BT    16384
#define BRNN  (Bb*RNN)
#define SMEM_BIG 197632   // 2 x 96KB chunk buffers + align

// ---------------- device scratch -------------------------------------------
// Row order everywhere: R = t*512 + b. Gate cols interleaved: n' = r*4 + g.
__device__ float g_Z[BT * G4];
__device__ float g_hall[(Tt + 1) * BRNN];      // slot t+1 = h after step t
__device__ float g_c0[BRNN];
__device__ float g_c1[BRNN];
__device__ float g_part[2 * Bb * G4];          // split-K partials (n' cols)
__device__ __align__(16) unsigned short g_Xs[3 * 128 * 10 * 8192]; // [3][128 mt][10 ch] 16KB
__device__ __align__(16) unsigned short g_Ws[3 * 16 * 10 * 8192];  // [3][16 nt][10 ch] 16KB
__device__ __align__(16) unsigned short g_Rs[3 * 16 * 8 * 8192];   // [3][16 nt][8 ch] 16KB
__device__ __align__(16) unsigned short g_hs[3 * 4 * 8 * 8192];    // [3][4 mt][8 ch] 16KB

// ---------------- PTX helpers ----------------------------------------------
static __device__ __forceinline__ uint32_t s2u(const void* p) {
    uint32_t a;
    asm("{ .reg .u64 t; cvta.to.shared.u64 t, %1; cvt.u32.u64 %0, t; }" : "=r"(a) : "l"(p));
    return a;
}
static __device__ __forceinline__ void cp16(uint32_t d, const void* s) {
    asm volatile("cp.async.cg.shared.global [%0], [%1], 16;" :: "r"(d), "l"(s));
}
#define CP_COMMIT() asm volatile("cp.async.commit_group;" ::: "memory")
#define CP_WAIT(n)  asm volatile("cp.async.wait_group %0;" :: "n"(n) : "memory")

static __device__ __forceinline__ void ldsm4(uint32_t* r, uint32_t a) {
    asm volatile("ldmatrix.sync.aligned.m8n8.x4.shared.b16 {%0,%1,%2,%3}, [%4];"
        : "=r"(r[0]), "=r"(r[1]), "=r"(r[2]), "=r"(r[3]) : "r"(a));
}
static __device__ __forceinline__ void ldsm2(uint32_t* r, uint32_t a) {
    asm volatile("ldmatrix.sync.aligned.m8n8.x2.shared.b16 {%0,%1}, [%2];"
        : "=r"(r[0]), "=r"(r[1]) : "r"(a));
}
static __device__ __forceinline__ void mma16816(float* d, const uint32_t* a, const uint32_t* b) {
    asm volatile("mma.sync.aligned.m16n8k16.row.col.f32.bf16.bf16.f32 "
        "{%0,%1,%2,%3}, {%4,%5,%6,%7}, {%8,%9}, {%0,%1,%2,%3};"
        : "+f"(d[0]), "+f"(d[1]), "+f"(d[2]), "+f"(d[3])
        : "r"(a[0]), "r"(a[1]), "r"(a[2]), "r"(a[3]), "r"(b[0]), "r"(b[1]));
}

// ---------------- split helpers --------------------------------------------
static __device__ __forceinline__ void split3(float x, unsigned short& s1,
                                              unsigned short& s2, unsigned short& s3) {
    __nv_bfloat16 b1 = __float2bfloat16_rn(x);
    float r1 = x - __bfloat162float(b1);
    __nv_bfloat16 b2 = __float2bfloat16_rn(r1);
    float r2 = r1 - __bfloat162float(b2);
    __nv_bfloat16 b3 = __float2bfloat16_rn(r2);
    s1 = __bfloat16_as_ushort(b1); s2 = __bfloat16_as_ushort(b2); s3 = __bfloat16_as_ushort(b3);
}
static __device__ __forceinline__ uint32_t swz(uint32_t o) { return o ^ ((o >> 3) & 0x70); }
static __device__ __forceinline__ void put_split4(char* base, int s_mul, int mt, int nch,
                                                  int c, int rb, int kk, float4 v) {
    uint32_t sw = swz(((uint32_t)(rb >> 3) << 10) + ((uint32_t)(rb & 7) << 7) + ((uint32_t)kk << 1));
    float xs[4] = {v.x, v.y, v.z, v.w};
    unsigned short a[3][4];
    #pragma unroll
    for (int i = 0; i < 4; i++) split3(xs[i], a[0][i], a[1][i], a[2][i]);
    #pragma unroll
    for (int s = 0; s < 3; s++) {
        ushort4 o = make_ushort4(a[s][0], a[s][1], a[s][2], a[s][3]);
        *(ushort4*)(base + ((size_t)(s * s_mul + mt) * nch + c) * 16384 + sw) = o;
    }
}
__device__ __forceinline__ float sigm(float x) { return 1.f / (1.f + expf(-x)); }

// ---------------- prep kernels ----------------------------------------------
// X rows in R = t*512 + b order
__global__ void assemble_splitX_kernel(const float* __restrict__ f_pool,
                                       const float* __restrict__ gt) {
    int idx = blockIdx.x * blockDim.x + threadIdx.x;
    if (idx >= BT * 160) return;
    int R = idx / 160, k0 = (idx - R * 160) * 4;
    int t = R >> 9, b = R & 511;
    float4 v;
    if (k0 < DEPTH) v = *(const float4*)(f_pool + ((size_t)b * Tt + t) * DEPTH + k0);
    else {
        v = (t == 0) ? make_float4(0.f, 0.f, 0.f, 0.f)
                     : *(const float4*)(gt + ((size_t)b * Tt + t - 1) * NCC + (k0 - DEPTH));
    }
    put_split4((char*)g_Xs, 128, R >> 7, 10, k0 >> 6, R & 127, k0 & 63, v);
}

// W, rec: columns permuted n -> n' = r*4 + g  (n = g*512 + r)
__global__ void split_W_kernel(const float* __restrict__ W) {
    int idx = blockIdx.x * blockDim.x + threadIdx.x;
    if (idx >= 160 * 2048) return;
    int kc = idx >> 11, n = idx & 2047, k0 = kc * 4;
    int g = n >> 9, r = n & 511, np = r * 4 + g;
    float4 v;
    v.x = W[(size_t)(k0 + 0) * G4 + n]; v.y = W[(size_t)(k0 + 1) * G4 + n];
    v.z = W[(size_t)(k0 + 2) * G4 + n]; v.w = W[(size_t)(k0 + 3) * G4 + n];
    put_split4((char*)g_Ws, 16, np >> 7, 10, k0 >> 6, np & 127, k0 & 63, v);
}

__global__ void split_rec_kernel(const float* __restrict__ rec) {
    int idx = blockIdx.x * blockDim.x + threadIdx.x;
    if (idx >= 128 * 2048) return;
    int kc = idx >> 11, n = idx & 2047, k0 = kc * 4;
    int g = n >> 9, r = n & 511, np = r * 4 + g;
    float4 v;
    v.x = rec[(size_t)(k0 + 0) * G4 + n]; v.y = rec[(size_t)(k0 + 1) * G4 + n];
    v.z = rec[(size_t)(k0 + 2) * G4 + n]; v.w = rec[(size_t)(k0 + 3) * G4 + n];
    put_split4((char*)g_Rs, 16, np >> 7, 8, k0 >> 6, np & 127, k0 & 63, v);
}

// ============ Z slab GEMM: g_Z[rows mt0*128 ..] = X@W + bias ================
// grid(16 nt, 16 mt) covers 2048 rows = 4 time steps per slab.
__global__ __launch_bounds__(256) void hmma_Z_slab_kernel(int mt0, const float* __restrict__ bias) {
    extern __shared__ char dsm[];
    const char* A8 = (const char*)g_Xs;
    const char* B8 = (const char*)g_Ws;
    const int tid = threadIdx.x, lane = tid & 31, wid = tid >> 5;
    const int mt = mt0 + blockIdx.y, nt = blockIdx.x;
    const int wm = wid & 1, wn = wid >> 1;
    uint32_t buf0 = (s2u(dsm) + 1023u) & ~1023u;

    const int l7 = lane & 7;
    const uint32_t xm = (uint32_t)l7 << 4;
    const int asub = lane >> 3;
    const uint32_t akoff = (uint32_t)(asub >> 1) * 16;
    const uint32_t bkoff = (uint32_t)((lane >> 3) & 1) * 16;
    uint32_t arb[4], brb[4];
    #pragma unroll
    for (int m4 = 0; m4 < 4; m4++) {
        int row = wm * 64 + m4 * 16 + (asub & 1) * 8 + l7;
        arb[m4] = (uint32_t)(row >> 3) * 1024u + (uint32_t)l7 * 128u;
    }
    #pragma unroll
    for (int n4 = 0; n4 < 4; n4++) {
        int row = wn * 32 + n4 * 8 + l7;
        brb[n4] = (uint32_t)(row >> 3) * 1024u + (uint32_t)l7 * 128u + 49152u;
    }

    float acc[4][4][4];
    #pragma unroll
    for (int m4 = 0; m4 < 4; m4++)
        #pragma unroll
        for (int n4 = 0; n4 < 4; n4++)
            #pragma unroll
            for (int e = 0; e < 4; e++) acc[m4][n4][e] = 0.f;

    auto load_chunk = [&](int c, int bb) {
        uint32_t sb = buf0 + (uint32_t)bb * 98304u;
        #pragma unroll
        for (int tau = 0; tau < 6; tau++) {
            const char* g = (tau < 3)
                ? A8 + ((size_t)(tau * 128 + mt) * 10 + c) * 16384
                : B8 + ((size_t)((tau - 3) * 16 + nt) * 10 + c) * 16384;
            uint32_t sdst = sb + (uint32_t)tau * 16384u + (uint32_t)tid * 16u;
            const char* gs = g + tid * 16;
            #pragma unroll
            for (int u = 0; u < 4; u++) cp16(sdst + u * 4096u, gs + u * 4096);
        }
    };

    load_chunk(0, 0);
    CP_COMMIT();
    for (int c = 0; c < 10; c++) {
        int cur = c & 1;
        if (c + 1 < 10) { load_chunk(c + 1, cur ^ 1); CP_COMMIT(); CP_WAIT(1); }
        else CP_WAIT(0);
        __syncthreads();
        uint32_t sb = buf0 + (uint32_t)cur * 98304u;
        #pragma unroll
        for (int ks = 0; ks < 4; ks++) {
            uint32_t kb = (uint32_t)ks * 32;
            uint32_t a[3][4][4];
            #pragma unroll
            for (int s = 0; s < 3; s++) {
                uint32_t ab = sb + (uint32_t)s * 16384u + ((kb + akoff) ^ xm);
                #pragma unroll
                for (int m4 = 0; m4 < 4; m4++) ldsm4(a[s][m4], ab + arb[m4]);
            }
            #pragma unroll
            for (int j = 0; j < 3; j++) {
                uint32_t b[4][2];
                uint32_t bbq = sb + (uint32_t)j * 16384u + ((kb + bkoff) ^ xm);
                #pragma unroll
                for (int n4 = 0; n4 < 4; n4++) ldsm2(b[n4], bbq + brb[n4]);
                #pragma unroll
                for (int i = 0; i + j < 3; i++)
                    #pragma unroll
                    for (int m4 = 0; m4 < 4; m4++)
                        #pragma unroll
                        for (int n4 = 0; n4 < 4; n4++)
                            mma16816(acc[m4][n4], a[i][m4], b[n4]);
            }
        }
        __syncthreads();
    }

    #pragma unroll
    for (int m4 = 0; m4 < 4; m4++) {
        int grow = mt * 128 + wm * 64 + m4 * 16 + (lane >> 2);
        #pragma unroll
        for (int n4 = 0; n4 < 4; n4++) {
            int gcol = nt * 128 + wn * 32 + n4 * 8 + (lane & 3) * 2;
            float b0 = bias[(gcol & 3) * 512 + (gcol >> 2)];
            float b1 = bias[((gcol + 1) & 3) * 512 + ((gcol + 1) >> 2)];
            float2 v;
            v.x = acc[m4][n4][0] + b0; v.y = acc[m4][n4][1] + b1;
            *(float2*)(g_Z + (size_t)grow * G4 + gcol) = v;
            v.x = acc[m4][n4][2] + b0; v.y = acc[m4][n4][3] + b1;
            *(float2*)(g_Z + (size_t)(grow + 8) * G4 + gcol) = v;
        }
    }
}

// ============ step GEMM: g_part[kz] = h @ rec (split-K=2) ===================
// grid(16 nt, 4 mt, 2 kz), 128x128 tile, chunks kz*4 .. kz*4+3.
__global__ __launch_bounds__(256) void hmma_step_kernel() {
    extern __shared__ char dsm[];
    const char* A8 = (const char*)g_hs;
    const char* B8 = (const char*)g_Rs;
    const int tid = threadIdx.x, lane = tid & 31, wid = tid >> 5;
    const int mt = blockIdx.y, nt = blockIdx.x, kz = blockIdx.z;
    const int c0 = kz * 4, c1 = c0 + 4;
    const int wm = wid & 1, wn = wid >> 1;
    float* out = g_part + (size_t)kz * (Bb * G4);
    uint32_t buf0 = (s2u(dsm) + 1023u) & ~1023u;

    const int l7 = lane & 7;
    const uint32_t xm = (uint32_t)l7 << 4;
    const int asub = lane >> 3;
    const uint32_t akoff = (uint32_t)(asub >> 1) * 16;
    const uint32_t bkoff = (uint32_t)((lane >> 3) & 1) * 16;
    uint32_t arb[4], brb[4];
    #pragma unroll
    for (int m4 = 0; m4 < 4; m4++) {
        int row = wm * 64 + m4 * 16 + (asub & 1) * 8 + l7;
        arb[m4] = (uint32_t)(row >> 3) * 1024u + (uint32_t)l7 * 128u;
    }
    #pragma unroll
    for (int n4 = 0; n4 < 4; n4++) {
        int row = wn * 32 + n4 * 8 + l7;
        brb[n4] = (uint32_t)(row >> 3) * 1024u + (uint32_t)l7 * 128u + 49152u;
    }

    float acc[4][4][4];
    #pragma unroll
    for (int m4 = 0; m4 < 4; m4++)
        #pragma unroll
        for (int n4 = 0; n4 < 4; n4++)
            #pragma unroll
            for (int e = 0; e < 4; e++) acc[m4][n4][e] = 0.f;

    auto load_chunk = [&](int c, int bb) {
        uint32_t sb = buf0 + (uint32_t)bb * 98304u;
        #pragma unroll
        for (int tau = 0; tau < 6; tau++) {
            const char* g = (tau < 3)
                ? A8 + ((size_t)(tau * 4 + mt) * 8 + c) * 16384
                : B8 + ((size_t)((tau - 3) * 16 + nt) * 8 + c) * 16384;
            uint32_t sdst = sb + (uint32_t)tau * 16384u + (uint32_t)tid * 16u;
            const char* gs = g + tid * 16;
            #pragma unroll
            for (int u = 0; u < 4; u++) cp16(sdst + u * 4096u, gs + u * 4096);
        }
    };

    load_chunk(c0, 0);
    CP_COMMIT();
    for (int c = c0; c < c1; c++) {
        int cur = (c - c0) & 1;
        if (c + 1 < c1) { load_chunk(c + 1, cur ^ 1); CP_COMMIT(); CP_WAIT(1); }
        else CP_WAIT(0);
        __syncthreads();
        uint32_t sb = buf0 + (uint32_t)cur * 98304u;
        #pragma unroll
        for (int ks = 0; ks < 4; ks++) {
            uint32_t kb = (uint32_t)ks * 32;
            uint32_t a[3][4][4];
            #pragma unroll
            for (int s = 0; s < 3; s++) {
                uint32_t ab = sb + (uint32_t)s * 16384u + ((kb + akoff) ^ xm);
                #pragma unroll
                for (int m4 = 0; m4 < 4; m4++) ldsm4(a[s][m4], ab + arb[m4]);
            }
            #pragma unroll
            for (int j = 0; j < 3; j++) {
                uint32_t b[4][2];
                uint32_t bbq = sb + (uint32_t)j * 16384u + ((kb + bkoff) ^ xm);
                #pragma unroll
                for (int n4 = 0; n4 < 4; n4++) ldsm2(b[n4], bbq + brb[n4]);
                #pragma unroll
                for (int i = 0; i + j < 3; i++)
                    #pragma unroll
                    for (int m4 = 0; m4 < 4; m4++)
                        #pragma unroll
                        for (int n4 = 0; n4 < 4; n4++)
                            mma16816(acc[m4][n4], a[i][m4], b[n4]);
            }
        }
        __syncthreads();
    }

    #pragma unroll
    for (int m4 = 0; m4 < 4; m4++) {
        int grow = mt * 128 + wm * 64 + m4 * 16 + (lane >> 2);
        #pragma unroll
        for (int n4 = 0; n4 < 4; n4++) {
            int gcol = nt * 128 + wn * 32 + n4 * 8 + (lane & 3) * 2;
            float2 v;
            v.x = acc[m4][n4][0]; v.y = acc[m4][n4][1];
            *(float2*)(out + (size_t)grow * G4 + gcol) = v;
            v.x = acc[m4][n4][2]; v.y = acc[m4][n4][3];
            *(float2*)(out + (size_t)(grow + 8) * G4 + gcol) = v;
        }
    }
}

// ---------------- gate: Z(+parts) + c -> h, c, h-splits ---------------------
__global__ __launch_bounds__(256) void gate_kernel(int t) {
    int idx = blockIdx.x * blockDim.x + threadIdx.x;
    if (idx >= Bb * 128) return;
    int r4 = (idx & 127) * 4, b = idx >> 7;
    const float* __restrict__ c_prev = (t & 1) ? g_c1 : g_c0;
    float* __restrict__ c_out = (t & 1) ? g_c0 : g_c1;
    float* __restrict__ h_out = g_hall + (size_t)(t + 1) * BRNN;

    const float* zb = g_Z + ((size_t)(t * Bb + b)) * G4 + r4 * 4;
    const float* p0 = g_part + (size_t)b * G4 + r4 * 4;
    const float* p1 = p0 + (size_t)Bb * G4;
    float4 cp = (t == 0) ? make_float4(0.f, 0.f, 0.f, 0.f)
                         : *(const float4*)(c_prev + (size_t)b * RNN + r4);
    float cpv[4] = {cp.x, cp.y, cp.z, cp.w};
    float4 cv, hv;
    float* cvp = &cv.x; float* hvp = &hv.x;
    #pragma unroll
    for (int u = 0; u < 4; u++) {
        float4 z = *(const float4*)(zb + u * 4);
        if (t > 0) {
            float4 p = *(const float4*)(p0 + u * 4);
            float4 q = *(const float4*)(p1 + u * 4);
            z.x += p.x + q.x; z.y += p.y + q.y; z.z += p.z + q.z; z.w += p.w + q.w;
        }
        float c2 = sigm(z.y) * cpv[u] + sigm(z.x) * tanhf(z.z);
        float h2 = sigm(z.w) * tanhf(c2);
        cvp[u] = c2; hvp[u] = h2;
    }
    *(float4*)(c_out + (size_t)b * RNN + r4) = cv;
    *(float4*)(h_out + (size_t)b * RNN + r4) = hv;
    put_split4((char*)g_hs, 4, b >> 7, 8, r4 >> 6, b & 127, r4 & 63, hv);
}

// ---------------- logits + argmax (exact fp32, 64-row tiles, 256 CTAs) ------
__global__ __launch_bounds__(256) void logits_argmax_kernel(
    const float* __restrict__ sw_, const float* __restrict__ sb_, float* __restrict__ out) {
    __shared__ float As[2][8][68];
    __shared__ float Bs[2][8][128];
    const int by = blockIdx.x, tid = threadIdx.x;
    const int tx = tid & 15, ty = tid >> 4;
    const int la_r = tid >> 2, la_k = (tid & 3) * 2;
    const int lb_k = tid >> 5, lb_j = (tid & 31) * 4;
    const float* Aptr = g_hall + BRNN + (size_t)(by * 64 + la_r) * RNN + la_k;
    const float* Bptr = sw_ + (size_t)lb_k * NCC + lb_j;

    float acc[4][8];
    #pragma unroll
    for (int i = 0; i < 4; i++)
        #pragma unroll
        for (int j = 0; j < 8; j++) acc[i][j] = 0.f;

    float2 aN = *(const float2*)(Aptr);
    float4 bN = *(const float4*)(Bptr);
    int buf = 0;
    for (int k0 = 0; k0 < RNN; k0 += 8) {
        As[buf][la_k + 0][la_r] = aN.x; As[buf][la_k + 1][la_r] = aN.y;
        *(float4*)&Bs[buf][lb_k][lb_j] = bN;
        if (k0 + 8 < RNN) {
            aN = *(const float2*)(Aptr + k0 + 8);
            bN = *(const float4*)(Bptr + (size_t)(k0 + 8) * NCC);
        }
        __syncthreads();
        #pragma unroll
        for (int kk = 0; kk < 8; kk++) {
            float av[4], bv[8];
            #pragma unroll
            for (int i = 0; i < 4; i++) av[i] = As[buf][kk][ty * 4 + i];
            #pragma unroll
            for (int j = 0; j < 8; j++) bv[j] = Bs[buf][kk][tx * 8 + j];
            #pragma unroll
            for (int i = 0; i < 4; i++)
                #pragma unroll
                for (int j = 0; j < 8; j++) acc[i][j] += av[i] * bv[j];
        }
        buf ^= 1;
    }
    #pragma unroll
    for (int i = 0; i < 4; i++) {
        float best = -1e30f; int bidx = 0;
        #pragma unroll
        for (int j = 0; j < 8; j++) {
            float v = acc[i][j] + sb_[tx * 8 + j];
            if (v > best) { best = v; bidx = tx * 8 + j; }
        }
        #pragma unroll
        for (int off = 8; off >= 1; off >>= 1) {
            float ob = __shfl_xor_sync(0xffffffffu, best, off);
            int oi = __shfl_xor_sync(0xffffffffu, bidx, off);
            if (ob > best || (ob == best && oi < bidx)) { best = ob; bidx = oi; }
        }
        int R = by * 64 + ty * 4 + i;     // R = t*512 + b
        int t = R >> 9, b = R & 511;
        float* orow = out + (size_t)b * (Tt * NCC) + t * NCC;
        #pragma unroll
        for (int j = 0; j < 8; j++) { int col = tx * 8 + j; orow[col] = (col == bidx) ? 1.f : 0.f; }
    }
}

__global__ void copy_final_kernel(float* __restrict__ out) {
    int i = blockIdx.x * blockDim.x + threadIdx.x;
    if (i < BRNN) {
        out[BT * NCC + i] = g_hall[(size_t)Tt * BRNN + i];
        out[BT * NCC + BRNN + i] = g_c0[i];   // t=31 odd -> wrote g_c0
    }
}

// ---------------- launch -----------------------------------------------------
extern "C" void kernel_launch(void* const* d_in, const int* in_sizes, int n_in,
                              void* d_out, int out_size) {
    const float* f_pool = (const float*)d_in[0];
    const float* gt     = (const float*)d_in[1];
    const float* W      = (const float*)d_in[2];
    const float* rec    = (const float*)d_in[3];
    const float* bias   = (const float*)d_in[4];
    const float* sw_    = (const float*)d_in[5];
    const float* sb_    = (const float*)d_in[6];
    float* out = (float*)d_out;

    // one-time host-side resources (no device memory)
    static cudaStream_t s1 = nullptr;
    static cudaEvent_t evFork = nullptr;
    static cudaEvent_t evSlab[8];
    if (!s1) {
        cudaStreamCreateWithFlags(&s1, cudaStreamNonBlocking);
        cudaEventCreateWithFlags(&evFork, cudaEventDisableTiming);
        for (int s = 0; s < 8; s++)
            cudaEventCreateWithFlags(&evSlab[s], cudaEventDisableTiming);
        cudaFuncSetAttribute(hmma_Z_slab_kernel, cudaFuncAttributeMaxDynamicSharedMemorySize, SMEM_BIG);
        cudaFuncSetAttribute(hmma_step_kernel, cudaFuncAttributeMaxDynamicSharedMemorySize, SMEM_BIG);
    }

    // prep on default stream
    assemble_splitX_kernel<<<(BT * 160 + 255) / 256, 256>>>(f_pool, gt);
    split_W_kernel<<<(160 * 2048 + 255) / 256, 256>>>(W);
    split_rec_kernel<<<(128 * 2048 + 255) / 256, 256>>>(rec);

    // fork: Z slabs on s1
    cudaEventRecord(evFork, 0);
    cudaStreamWaitEvent(s1, evFork, 0);
    for (int s = 0; s < 8; s++) {
        hmma_Z_slab_kernel<<<dim3(16, 16), 256, SMEM_BIG, s1>>>(16 * s, bias);
        cudaEventRecord(evSlab[s], s1);
    }

    // steps on default stream; gate t needs Z slab t/4
    const int gate_blocks = (Bb * 128 + 255) / 256;
    for (int t = 0; t < Tt; t++) {
        if ((t & 3) == 0) cudaStreamWaitEvent(0, evSlab[t >> 2], 0);
        if (t > 0)
            hmma_step_kernel<<<dim3(16, 4, 2), 256, SMEM_BIG>>>();
        gate_kernel<<<gate_blocks, 256>>>(t);
    }

    // join remaining forked work (already waited via evSlab[7] at t=28; explicit for safety)
    cudaStreamWaitEvent(0, evSlab[7], 0);

    logits_argmax_kernel<<<256, 256>>>(sw_, sb_, out);
    copy_final_kernel<<<(BRNN + 255) / 256, 256>>>(out);
}